// round 1
// baseline (speedup 1.0000x reference)
#include <cuda_runtime.h>
#include <cstdint>

#define B_DIM 2048
#define NLEAF 1024
#define FDIM 32
#define HDIM 128
#define ODIM 32

// Ping-pong scratch for tree levels (no allocations allowed -> device globals)
__device__ __align__(256) float g_bufA[(size_t)B_DIM * NLEAF * ODIM];        // 256 MB
__device__ __align__(256) float g_bufB[(size_t)B_DIM * (NLEAF / 2) * ODIM];  // 128 MB

// ---------------- packed f32x2 helpers (sm_100+) ----------------
__device__ __forceinline__ unsigned long long pack2(float x) {
    unsigned long long r;
    asm("mov.b64 %0, {%1, %1};" : "=l"(r) : "f"(x));
    return r;
}
__device__ __forceinline__ void ffma2(unsigned long long& d, unsigned long long a,
                                      unsigned long long b) {
    asm("fma.rn.f32x2 %0, %1, %2, %3;" : "=l"(d) : "l"(a), "l"(b), "l"(d));
}

// ---------------- cooperative smem copy ----------------
__device__ __forceinline__ void copy4(float* dst, const float* __restrict__ src, int nfloats) {
    const float4* s = (const float4*)src;
    float4* d = (float4*)dst;
    int n4 = nfloats >> 2;
    for (int i = threadIdx.x; i < n4; i += blockDim.x) d[i] = s[i];
}

// ---------------- one MLP layer on a 64-row tile ----------------
// 256 threads; TM=4 rows x TN cols per thread. K = input dim, N = output dim.
template <int K, int N, int TN, bool RELU>
__device__ __forceinline__ void mlp_layer(const float* __restrict__ sIn, int inLd,
                                          const float* __restrict__ sW,
                                          const float* __restrict__ sB,
                                          float* __restrict__ sOut, int outLd) {
    constexpr int TM = 4;
    constexpr int NP = TN / 2;
    const int tid = threadIdx.x;
    const int rg = tid >> 4;   // 16 row-groups * 4 rows = 64
    const int cg = tid & 15;   // 16 col-groups * TN cols = N
    const int r0 = rg * TM;
    const int c0 = cg * TN;

    unsigned long long acc[TM][NP];
#pragma unroll
    for (int i = 0; i < TM; i++)
#pragma unroll
        for (int j = 0; j < NP; j++) acc[i][j] = 0ull;

    const float* wp = sW + c0;
#pragma unroll 4
    for (int k = 0; k < K; k++) {
        unsigned long long bv[NP];
        const unsigned long long* wv = reinterpret_cast<const unsigned long long*>(wp + k * N);
#pragma unroll
        for (int j = 0; j < NP; j++) bv[j] = wv[j];
#pragma unroll
        for (int i = 0; i < TM; i++) {
            unsigned long long av = pack2(sIn[(r0 + i) * inLd + k]);
#pragma unroll
            for (int j = 0; j < NP; j++) ffma2(acc[i][j], av, bv[j]);
        }
    }

#pragma unroll
    for (int i = 0; i < TM; i++) {
#pragma unroll
        for (int j = 0; j < NP; j++) {
            float2 v = *reinterpret_cast<float2*>(&acc[i][j]);
            float o0 = v.x + sB[c0 + 2 * j];
            float o1 = v.y + sB[c0 + 2 * j + 1];
            if (RELU) {
                o0 = fmaxf(o0, 0.f);
                o1 = fmaxf(o1, 0.f);
            }
            sOut[(r0 + i) * outLd + c0 + 2 * j] = o0;
            sOut[(r0 + i) * outLd + c0 + 2 * j + 1] = o1;
        }
    }
}

// ---------------- leaf stage: (M,32) -> 32->128->128->32 ----------------
__global__ void __launch_bounds__(256, 1)
    leaf_kernel(const float* __restrict__ X, const float* __restrict__ W1,
                const float* __restrict__ B1, const float* __restrict__ W2,
                const float* __restrict__ B2, const float* __restrict__ W3,
                const float* __restrict__ B3, float* __restrict__ Y, int numTiles) {
    extern __shared__ float sm[];
    float* sW1 = sm;                 // 32*128
    float* sW2 = sW1 + 32 * 128;     // 128*128
    float* sW3 = sW2 + 128 * 128;    // 128*32
    float* sB1 = sW3 + 128 * 32;     // 128
    float* sB2 = sB1 + 128;          // 128
    float* sB3 = sB2 + 128;          // 32
    float* sX = sB3 + 32;            // 64*36 (padded)
    float* sH1 = sX + 64 * 36;       // 64*132 (padded)
    float* sH2 = sH1 + 64 * 132;     // 64*132

    copy4(sW1, W1, 32 * 128);
    copy4(sW2, W2, 128 * 128);
    copy4(sW3, W3, 128 * 32);
    copy4(sB1, B1, 128);
    copy4(sB2, B2, 128);
    copy4(sB3, B3, 32);
    __syncthreads();

    const int t = threadIdx.x;
    for (int tile = blockIdx.x; tile < numTiles; tile += gridDim.x) {
        const float4* src = (const float4*)(X + (size_t)tile * 64 * 32);
#pragma unroll
        for (int i = 0; i < 2; i++) {
            int idx = t + i * 256;  // 512 float4 = 64 rows x 8
            int row = idx >> 3, q = idx & 7;
            *(float4*)(sX + row * 36 + q * 4) = src[idx];
        }
        __syncthreads();
        mlp_layer<32, 128, 8, true>(sX, 36, sW1, sB1, sH1, 132);
        __syncthreads();
        mlp_layer<128, 128, 8, true>(sH1, 132, sW2, sB2, sH2, 132);
        __syncthreads();
        mlp_layer<128, 32, 2, false>(sH2, 132, sW3, sB3, sH1, 36);
        __syncthreads();
        float4* dstv = (float4*)(Y + (size_t)tile * 64 * 32);
#pragma unroll
        for (int i = 0; i < 2; i++) {
            int idx = t + i * 256;
            int row = idx >> 3, q = idx & 7;
            dstv[idx] = *(float4*)(sH1 + row * 36 + q * 4);
        }
        __syncthreads();
    }
}

// ---------------- join stage: concat(feats32, children64) -> 96->128->128->32 ----
__global__ void __launch_bounds__(256, 1)
    join_kernel(const float* __restrict__ internal, int off, int nShift,
                const float* __restrict__ prev, const float* __restrict__ W1,
                const float* __restrict__ B1, const float* __restrict__ W2,
                const float* __restrict__ B2, const float* __restrict__ W3,
                const float* __restrict__ B3, float* __restrict__ Y, int numTiles) {
    extern __shared__ float sm[];
    float* sW1 = sm;                 // 96*128
    float* sW2 = sW1 + 96 * 128;     // 128*128
    float* sW3 = sW2 + 128 * 128;    // 128*32
    float* sB1 = sW3 + 128 * 32;
    float* sB2 = sB1 + 128;
    float* sB3 = sB2 + 128;
    float* sX = sB3 + 32;            // 64*100 (padded 96->100)
    float* sH1 = sX + 64 * 100;      // 64*132
    float* sH2 = sH1 + 64 * 132;     // 64*132

    copy4(sW1, W1, 96 * 128);
    copy4(sW2, W2, 128 * 128);
    copy4(sW3, W3, 128 * 32);
    copy4(sB1, B1, 128);
    copy4(sB2, B2, 128);
    copy4(sB3, B3, 32);
    __syncthreads();

    const int t = threadIdx.x;
    const int nMask = (1 << nShift) - 1;
    const int row = t >> 2;        // 4 threads per row
    const int sub = t & 3;         // each does 6 float4 of the 24/row

    for (int tile = blockIdx.x; tile < numTiles; tile += gridDim.x) {
        // assemble xin row = [feats(32) | child0(32) | child1(32)]
        {
            int m = tile * 64 + row;
            int bidx = m >> nShift;
            int i = m & nMask;
            const float4* frow =
                (const float4*)(internal + ((size_t)bidx * (NLEAF - 1) + off + i) * FDIM);
            const float4* crow =
                (const float4*)(prev + ((size_t)(bidx << (nShift + 1)) + 2 * (size_t)i) * ODIM);
#pragma unroll
            for (int jj = 0; jj < 6; jj++) {
                int q = sub * 6 + jj;  // 0..23
                float4 v = (q < 8) ? frow[q] : crow[q - 8];
                *(float4*)(sX + row * 100 + q * 4) = v;
            }
        }
        __syncthreads();
        mlp_layer<96, 128, 8, true>(sX, 100, sW1, sB1, sH1, 132);
        __syncthreads();
        mlp_layer<128, 128, 8, true>(sH1, 132, sW2, sB2, sH2, 132);
        __syncthreads();
        mlp_layer<128, 32, 2, false>(sH2, 132, sW3, sB3, sX, 36);
        __syncthreads();
        float4* dstv = (float4*)(Y + (size_t)tile * 64 * 32);
#pragma unroll
        for (int i = 0; i < 2; i++) {
            int idx = t + i * 256;
            int r2 = idx >> 3, q = idx & 7;
            dstv[idx] = *(float4*)(sX + r2 * 36 + q * 4);
        }
        __syncthreads();
    }
}

__global__ void gather_kernel(const float* __restrict__ src, float* __restrict__ out) {
    int b = blockIdx.x * blockDim.x + threadIdx.x;
    if (b < B_DIM) out[b] = src[(size_t)b * ODIM];
}

extern "C" void kernel_launch(void* const* d_in, const int* in_sizes, int n_in, void* d_out,
                              int out_size) {
    const float* leaf = (const float*)d_in[0];
    const float* internal = (const float*)d_in[1];
    const float* sW1 = (const float*)d_in[2];
    const float* sb1 = (const float*)d_in[3];
    const float* sW2 = (const float*)d_in[4];
    const float* sb2 = (const float*)d_in[5];
    const float* sW3 = (const float*)d_in[6];
    const float* sb3 = (const float*)d_in[7];
    const float* jW1 = (const float*)d_in[8];
    const float* jb1 = (const float*)d_in[9];
    const float* jW2 = (const float*)d_in[10];
    const float* jb2 = (const float*)d_in[11];
    const float* jW3 = (const float*)d_in[12];
    const float* jb3 = (const float*)d_in[13];
    float* out = (float*)d_out;

    float *bufA, *bufB;
    cudaGetSymbolAddress((void**)&bufA, g_bufA);
    cudaGetSymbolAddress((void**)&bufB, g_bufB);

    const int leafSm =
        (32 * 128 + 128 * 128 + 128 * 32 + 128 + 128 + 32 + 64 * 36 + 2 * 64 * 132) * 4;
    const int joinSm =
        (96 * 128 + 128 * 128 + 128 * 32 + 128 + 128 + 32 + 64 * 100 + 2 * 64 * 132) * 4;
    cudaFuncSetAttribute(leaf_kernel, cudaFuncAttributeMaxDynamicSharedMemorySize, leafSm);
    cudaFuncSetAttribute(join_kernel, cudaFuncAttributeMaxDynamicSharedMemorySize, joinSm);

    int sms = 148;
    cudaDeviceGetAttribute(&sms, cudaDevAttrMultiProcessorCount, 0);

    const int leafTiles = (B_DIM * NLEAF) / 64;  // 32768
    leaf_kernel<<<sms, 256, leafSm>>>(leaf, sW1, sb1, sW2, sb2, sW3, sb3, bufA, leafTiles);

    float* src = bufA;
    float* dst = bufB;
    int off = 0;
    for (int sh = 9; sh >= 0; sh--) {
        int n = 1 << sh;
        int tiles = (B_DIM * n) / 64;
        join_kernel<<<sms, 256, joinSm>>>(internal, off, sh, src, jW1, jb1, jW2, jb2, jW3, jb3,
                                          dst, tiles);
        off += n;
        float* tmp = src;
        src = dst;
        dst = tmp;
    }
    gather_kernel<<<(B_DIM + 255) / 256, 256>>>(src, out);
}

// round 5
// speedup vs baseline: 1.4658x; 1.4658x over previous
#include <cuda_runtime.h>
#include <cstdint>

#define B_DIM 2048
#define NLEAF 1024
#define FDIM 32
#define HDIM 128
#define ODIM 32

// Ping-pong scratch for tree levels (no allocations allowed -> device globals)
__device__ __align__(256) float g_bufA[(size_t)B_DIM * NLEAF * ODIM];        // 256 MB
__device__ __align__(256) float g_bufB[(size_t)B_DIM * (NLEAF / 2) * ODIM];  // 128 MB

// ---------------- packed f32x2 helpers (sm_100+) ----------------
__device__ __forceinline__ unsigned long long pack2(float x) {
    unsigned long long r;
    asm("mov.b64 %0, {%1, %1};" : "=l"(r) : "f"(x));
    return r;
}
__device__ __forceinline__ void ffma2(unsigned long long& d, unsigned long long a,
                                      unsigned long long b) {
    asm("fma.rn.f32x2 %0, %1, %2, %3;" : "=l"(d) : "l"(a), "l"(b), "l"(d));
}

// ---------------- cooperative smem copy ----------------
__device__ __forceinline__ void copy4(float* dst, const float* __restrict__ src, int nfloats) {
    const float4* s = (const float4*)src;
    float4* d = (float4*)dst;
    int n4 = nfloats >> 2;
    for (int i = threadIdx.x; i < n4; i += blockDim.x) d[i] = s[i];
}

// ---------------- one MLP layer on a 64-row tile ----------------
// 256 threads; TM=4 rows x TN cols per thread. K = input dim, N = output dim.
// Column ownership: thread cg owns columns {cg*2 + 32*j} -> weight LDS.64 lanes
// are at 8B stride = conflict-free 128B wavefronts; same for output STS.64.
template <int K, int N, int TN, bool RELU>
__device__ __forceinline__ void mlp_layer(const float* __restrict__ sIn, int inLd,
                                          const float* __restrict__ sW,
                                          const float* __restrict__ sB,
                                          float* __restrict__ sOut, int outLd) {
    constexpr int TM = 4;
    constexpr int NP = TN / 2;
    const int tid = threadIdx.x;
    const int rg = tid >> 4;   // 16 row-groups * 4 rows = 64
    const int cg = tid & 15;
    const int r0 = rg * TM;

    unsigned long long acc[TM][NP];
#pragma unroll
    for (int i = 0; i < TM; i++)
#pragma unroll
        for (int j = 0; j < NP; j++) acc[i][j] = 0ull;

    const float* wBase = sW + cg * 2;  // + k*N + 32*j
#pragma unroll 4
    for (int k0 = 0; k0 < K; k0 += 4) {
        // vectorized activation loads: 4 k-values per row (broadcast across lanes)
        float a4[TM][4];
#pragma unroll
        for (int i = 0; i < TM; i++) {
            float4 v = *(const float4*)(sIn + (r0 + i) * inLd + k0);
            a4[i][0] = v.x; a4[i][1] = v.y; a4[i][2] = v.z; a4[i][3] = v.w;
        }
#pragma unroll
        for (int kk = 0; kk < 4; kk++) {
            unsigned long long bv[NP];
            const float* wr = wBase + (k0 + kk) * N;
#pragma unroll
            for (int j = 0; j < NP; j++)
                bv[j] = *reinterpret_cast<const unsigned long long*>(wr + 32 * j);
#pragma unroll
            for (int i = 0; i < TM; i++) {
                unsigned long long av = pack2(a4[i][kk]);
#pragma unroll
                for (int j = 0; j < NP; j++) ffma2(acc[i][j], av, bv[j]);
            }
        }
    }

#pragma unroll
    for (int j = 0; j < NP; j++) {
        const int c = cg * 2 + 32 * j;
        float2 bb = *(const float2*)(sB + c);
#pragma unroll
        for (int i = 0; i < TM; i++) {
            float2 v = *reinterpret_cast<float2*>(&acc[i][j]);
            float o0 = v.x + bb.x;
            float o1 = v.y + bb.y;
            if (RELU) {
                o0 = fmaxf(o0, 0.f);
                o1 = fmaxf(o1, 0.f);
            }
            *(float2*)(sOut + (r0 + i) * outLd + c) = make_float2(o0, o1);
        }
    }
}

// ---------------- leaf stage: (M,32) -> 32->128->128->32 ----------------
__global__ void __launch_bounds__(256, 1)
    leaf_kernel(const float* __restrict__ X, const float* __restrict__ W1,
                const float* __restrict__ B1, const float* __restrict__ W2,
                const float* __restrict__ B2, const float* __restrict__ W3,
                const float* __restrict__ B3, float* __restrict__ Y, int numTiles) {
    extern __shared__ float sm[];
    float* sW1 = sm;                 // 32*128
    float* sW2 = sW1 + 32 * 128;     // 128*128
    float* sW3 = sW2 + 128 * 128;    // 128*32
    float* sB1 = sW3 + 128 * 32;     // 128
    float* sB2 = sB1 + 128;          // 128
    float* sB3 = sB2 + 128;          // 32
    float* sX = sB3 + 32;            // 64*36 (padded)
    float* sH1 = sX + 64 * 36;       // 64*132 (padded)
    float* sH2 = sH1 + 64 * 132;     // 64*132

    copy4(sW1, W1, 32 * 128);
    copy4(sW2, W2, 128 * 128);
    copy4(sW3, W3, 128 * 32);
    copy4(sB1, B1, 128);
    copy4(sB2, B2, 128);
    copy4(sB3, B3, 32);
    __syncthreads();

    const int t = threadIdx.x;
    for (int tile = blockIdx.x; tile < numTiles; tile += gridDim.x) {
        const float4* src = (const float4*)(X + (size_t)tile * 64 * 32);
#pragma unroll
        for (int i = 0; i < 2; i++) {
            int idx = t + i * 256;  // 512 float4 = 64 rows x 8
            int row = idx >> 3, q = idx & 7;
            *(float4*)(sX + row * 36 + q * 4) = src[idx];
        }
        __syncthreads();
        mlp_layer<32, 128, 8, true>(sX, 36, sW1, sB1, sH1, 132);
        __syncthreads();
        mlp_layer<128, 128, 8, true>(sH1, 132, sW2, sB2, sH2, 132);
        __syncthreads();
        mlp_layer<128, 32, 2, false>(sH2, 132, sW3, sB3, sH1, 36);
        __syncthreads();
        float4* dstv = (float4*)(Y + (size_t)tile * 64 * 32);
#pragma unroll
        for (int i = 0; i < 2; i++) {
            int idx = t + i * 256;
            int row = idx >> 3, q = idx & 7;
            dstv[idx] = *(float4*)(sH1 + row * 36 + q * 4);
        }
        __syncthreads();
    }
}

// ---------------- join stage: concat(feats32, children64) -> 96->128->128->32 ----
__global__ void __launch_bounds__(256, 1)
    join_kernel(const float* __restrict__ internal, int off, int nShift,
                const float* __restrict__ prev, const float* __restrict__ W1,
                const float* __restrict__ B1, const float* __restrict__ W2,
                const float* __restrict__ B2, const float* __restrict__ W3,
                const float* __restrict__ B3, float* __restrict__ Y, int numTiles) {
    extern __shared__ float sm[];
    float* sW1 = sm;                 // 96*128
    float* sW2 = sW1 + 96 * 128;     // 128*128
    float* sW3 = sW2 + 128 * 128;    // 128*32
    float* sB1 = sW3 + 128 * 32;
    float* sB2 = sB1 + 128;
    float* sB3 = sB2 + 128;
    float* sX = sB3 + 32;            // 64*100 (padded 96->100)
    float* sH1 = sX + 64 * 100;      // 64*132
    float* sH2 = sH1 + 64 * 132;     // 64*132

    copy4(sW1, W1, 96 * 128);
    copy4(sW2, W2, 128 * 128);
    copy4(sW3, W3, 128 * 32);
    copy4(sB1, B1, 128);
    copy4(sB2, B2, 128);
    copy4(sB3, B3, 32);
    __syncthreads();

    const int t = threadIdx.x;
    const int nMask = (1 << nShift) - 1;
    const int row = t >> 2;        // 4 threads per row
    const int sub = t & 3;         // each does 6 float4 of the 24/row

    for (int tile = blockIdx.x; tile < numTiles; tile += gridDim.x) {
        // assemble xin row = [feats(32) | child0(32) | child1(32)]
        {
            int m = tile * 64 + row;
            int bidx = m >> nShift;
            int i = m & nMask;
            const float4* frow =
                (const float4*)(internal + ((size_t)bidx * (NLEAF - 1) + off + i) * FDIM);
            const float4* crow =
                (const float4*)(prev + ((size_t)(bidx << (nShift + 1)) + 2 * (size_t)i) * ODIM);
#pragma unroll
            for (int jj = 0; jj < 6; jj++) {
                int q = sub * 6 + jj;  // 0..23
                float4 v = (q < 8) ? frow[q] : crow[q - 8];
                *(float4*)(sX + row * 100 + q * 4) = v;
            }
        }
        __syncthreads();
        mlp_layer<96, 128, 8, true>(sX, 100, sW1, sB1, sH1, 132);
        __syncthreads();
        mlp_layer<128, 128, 8, true>(sH1, 132, sW2, sB2, sH2, 132);
        __syncthreads();
        mlp_layer<128, 32, 2, false>(sH2, 132, sW3, sB3, sX, 36);
        __syncthreads();
        float4* dstv = (float4*)(Y + (size_t)tile * 64 * 32);
#pragma unroll
        for (int i = 0; i < 2; i++) {
            int idx = t + i * 256;
            int r2 = idx >> 3, q = idx & 7;
            dstv[idx] = *(float4*)(sX + r2 * 36 + q * 4);
        }
        __syncthreads();
    }
}

__global__ void gather_kernel(const float* __restrict__ src, float* __restrict__ out) {
    int b = blockIdx.x * blockDim.x + threadIdx.x;
    if (b < B_DIM) out[b] = src[(size_t)b * ODIM];
}

extern "C" void kernel_launch(void* const* d_in, const int* in_sizes, int n_in, void* d_out,
                              int out_size) {
    const float* leaf = (const float*)d_in[0];
    const float* internal = (const float*)d_in[1];
    const float* sW1 = (const float*)d_in[2];
    const float* sb1 = (const float*)d_in[3];
    const float* sW2 = (const float*)d_in[4];
    const float* sb2 = (const float*)d_in[5];
    const float* sW3 = (const float*)d_in[6];
    const float* sb3 = (const float*)d_in[7];
    const float* jW1 = (const float*)d_in[8];
    const float* jb1 = (const float*)d_in[9];
    const float* jW2 = (const float*)d_in[10];
    const float* jb2 = (const float*)d_in[11];
    const float* jW3 = (const float*)d_in[12];
    const float* jb3 = (const float*)d_in[13];
    float* out = (float*)d_out;

    float *bufA, *bufB;
    cudaGetSymbolAddress((void**)&bufA, g_bufA);
    cudaGetSymbolAddress((void**)&bufB, g_bufB);

    const int leafSm =
        (32 * 128 + 128 * 128 + 128 * 32 + 128 + 128 + 32 + 64 * 36 + 2 * 64 * 132) * 4;
    const int joinSm =
        (96 * 128 + 128 * 128 + 128 * 32 + 128 + 128 + 32 + 64 * 100 + 2 * 64 * 132) * 4;
    cudaFuncSetAttribute(leaf_kernel, cudaFuncAttributeMaxDynamicSharedMemorySize, leafSm);
    cudaFuncSetAttribute(join_kernel, cudaFuncAttributeMaxDynamicSharedMemorySize, joinSm);

    int sms = 148;
    cudaDeviceGetAttribute(&sms, cudaDevAttrMultiProcessorCount, 0);

    const int leafTiles = (B_DIM * NLEAF) / 64;  // 32768
    leaf_kernel<<<sms, 256, leafSm>>>(leaf, sW1, sb1, sW2, sb2, sW3, sb3, bufA, leafTiles);

    float* src = bufA;
    float* dst = bufB;
    int off = 0;
    for (int sh = 9; sh >= 0; sh--) {
        int n = 1 << sh;
        int tiles = (B_DIM * n) / 64;
        join_kernel<<<sms, 256, joinSm>>>(internal, off, sh, src, jW1, jb1, jW2, jb2, jW3, jb3,
                                          dst, tiles);
        off += n;
        float* tmp = src;
        src = dst;
        dst = tmp;
    }
    gather_kernel<<<(B_DIM + 255) / 256, 256>>>(src, out);
}